// round 12
// baseline (speedup 1.0000x reference)
#include <cuda_runtime.h>
#include <cuda_fp16.h>
#include <cstdint>
#include <math.h>

// tril(A @ B), A,B lower-triangular fp32, N=4096.
// R12: fp16 2-term split GEMM (validated R11: rel_err 2.08e-4) with 64x64
// warp tiles: 12 ldm4 feed 64 HMMA per ks16 (halved LSU/MMA vs 64x32).
// 128-thread CTAs (4 warps, 2x2), 128x128 tile, 2 CTAs/SM (8 warps/SM) with
// no forced register cap (2x128x~200 regs = 51K < 64K RF). cp.async 3-stage
// ring from pre-split fp16 planes; one merged prepass kernel.
//   x = h + l (fp16 exact residual);  D = Ah*Bh + Al*Bh  (drop ~2^-11 term)

#define NDIM 4096
#define NB   32
#define BK   32
#define THREADS 128

#define ROWB  80               // 32 fp16 = 64B padded to 80B (conflict-free)
#define ST_AL 10240            // A hi at 0 (128*80), A lo, then B hi
#define ST_BH 20480
#define STAGE 30720
#define NSTG  3
#define SMEM_DYN (NSTG * STAGE)   // 92160/CTA; x2 CTAs = 184320 < 228KB

__device__ __align__(256) signed char g_Ah[(size_t)NDIM * NDIM * 2];
__device__ __align__(256) signed char g_Al[(size_t)NDIM * NDIM * 2];
__device__ __align__(256) signed char g_Bh[(size_t)NDIM * NDIM * 2];  // [n][k]

static __device__ __forceinline__ uint32_t smem_u32(const void* p) {
    uint32_t a;
    asm("{ .reg .u64 t; cvta.to.shared.u64 t, %1; cvt.u32.u64 %0, t; }"
        : "=r"(a) : "l"(p));
    return a;
}

static __device__ __forceinline__ uint32_t h2u(__half2 h) {
    return *reinterpret_cast<uint32_t*>(&h);
}

static __device__ __forceinline__ void split2(float x, float y,
                                              uint32_t& h, uint32_t& l) {
    __half2 hh = __floats2half2_rn(x, y);
    float rx = x - __half2float(__low2half(hh));
    float ry = y - __half2float(__high2half(hh));
    __half2 ll = __floats2half2_rn(rx, ry);
    h = h2u(hh);
    l = h2u(ll);
}

static __device__ __forceinline__ void ldm4(uint32_t d[4], uint32_t addr) {
    asm volatile("ldmatrix.sync.aligned.m8n8.x4.shared.b16 {%0,%1,%2,%3}, [%4];"
                 : "=r"(d[0]), "=r"(d[1]), "=r"(d[2]), "=r"(d[3]) : "r"(addr));
}

static __device__ __forceinline__ void mma_f16(float* c, const uint32_t* a,
                                               uint32_t b0, uint32_t b1) {
    asm volatile(
        "mma.sync.aligned.m16n8k16.row.col.f32.f16.f16.f32 "
        "{%0,%1,%2,%3}, {%4,%5,%6,%7}, {%8,%9}, {%0,%1,%2,%3};"
        : "+f"(c[0]), "+f"(c[1]), "+f"(c[2]), "+f"(c[3])
        : "r"(a[0]), "r"(a[1]), "r"(a[2]), "r"(a[3]), "r"(b0), "r"(b1));
}

static __device__ __forceinline__ void cp16(uint32_t dst, const void* src) {
    asm volatile("cp.async.cg.shared.global [%0], [%1], 16;"
                 :: "r"(dst), "l"(src) : "memory");
}
#define CP_COMMIT() asm volatile("cp.async.commit_group;" ::: "memory")
#define CP_WAIT2()  asm volatile("cp.async.wait_group 2;" ::: "memory")

// ---------------- merged prepass: A -> hi/lo planes; B -> Bh^T [n][k]
__global__ __launch_bounds__(256)
void prep_kernel(const float* __restrict__ A, const float* __restrict__ B) {
    __shared__ float tile[64][65];
    if (blockIdx.x < 16384) {
        // split A (layout kept: row-major = k-major)
        const size_t i4 = ((size_t)blockIdx.x * 256 + threadIdx.x) * 4;
        float4 v = *(const float4*)(A + i4);
        uint32_t h01, l01, h23, l23;
        split2(v.x, v.y, h01, l01);
        split2(v.z, v.w, h23, l23);
        *(uint2*)(g_Ah + i4 * 2) = make_uint2(h01, h23);
        *(uint2*)(g_Al + i4 * 2) = make_uint2(l01, l23);
    } else {
        // transpose + fp16-convert B hi plane
        const int bb = blockIdx.x - 16384;
        const int tid = threadIdx.x;
        const int kt = (bb & 63) * 64;
        const int nt = (bb >> 6) * 64;
        {
            const int nc4 = (tid & 15) * 4;
            const int kr0 = tid >> 4;
#pragma unroll
            for (int j = 0; j < 4; ++j) {
                const int kr = kr0 + 16 * j;
                float4 v = *(const float4*)(B + (size_t)(kt + kr) * NDIM + nt + nc4);
                tile[kr][nc4] = v.x; tile[kr][nc4 + 1] = v.y;
                tile[kr][nc4 + 2] = v.z; tile[kr][nc4 + 3] = v.w;
            }
        }
        __syncthreads();
        const int kw4 = (tid & 15) * 4;
        const int n0 = tid >> 4;
#pragma unroll
        for (int it = 0; it < 4; ++it) {
            const int n = n0 + 16 * it;
            __half2 h01 = __floats2half2_rn(tile[kw4][n], tile[kw4 + 1][n]);
            __half2 h23 = __floats2half2_rn(tile[kw4 + 2][n], tile[kw4 + 3][n]);
            const size_t o = ((size_t)(nt + n) * NDIM + kt + kw4) * 2;
            *(uint2*)(g_Bh + o) = make_uint2(h2u(h01), h2u(h23));
        }
    }
}

// ---------------- main GEMM: 128x128 tile, 4 warps of 64x64, 2 CTAs/SM
__global__ __launch_bounds__(THREADS, 2)
void trimm_f16(float* __restrict__ C)
{
    extern __shared__ __align__(128) char dyn_smem[];
    const uint32_t sbase = smem_u32(dyn_smem);

    const int tid  = threadIdx.x;
    const int wid  = tid >> 5;
    const int lane = tid & 31;

    // ---- block id -> (bi,bj), largest-K first ----
    int t = blockIdx.x;
    int g = (int)((sqrtf(8.0f * (float)t + 1.0f) - 1.0f) * 0.5f);
    while ((g + 1) * (g + 2) / 2 <= t) ++g;
    while (g * (g + 1) / 2 > t) --g;
    const int bj = t - g * (g + 1) / 2;
    const int bi = bj + (NB - 1) - g;
    const int bm0 = bi * 128, bn0 = bj * 128;
    const int nchunks = ((bm0 + 128) - bn0) >> 5;   // 4..128

    // warp grid 2(m) x 2(n): warp tile 64x64
    const int m0w = (wid & 1) * 64;
    const int n0w = (wid >> 1) * 64;

    // ---- cp.async: each thread owns one 64B row slice per plane ----
    const uint32_t dRow = (uint32_t)(tid * ROWB);
    const signed char* srcAh = g_Ah + ((size_t)(bm0 + tid) * NDIM + bn0) * 2;
    const signed char* srcAl = g_Al + ((size_t)(bm0 + tid) * NDIM + bn0) * 2;
    const signed char* srcBh = g_Bh + ((size_t)(bn0 + tid) * NDIM + bn0) * 2;

#define ISSUE_CP(c)                                                            \
    {                                                                          \
        const uint32_t sb = sbase + (uint32_t)((c) % NSTG) * STAGE;            \
        const int ko = (c) * (BK * 2);                                         \
        _Pragma("unroll")                                                      \
        for (int j = 0; j < 4; ++j)                                            \
            cp16(sb + dRow + 16 * j, srcAh + ko + 16 * j);                     \
        _Pragma("unroll")                                                      \
        for (int j = 0; j < 4; ++j)                                            \
            cp16(sb + ST_AL + dRow + 16 * j, srcAl + ko + 16 * j);             \
        _Pragma("unroll")                                                      \
        for (int j = 0; j < 4; ++j)                                            \
            cp16(sb + ST_BH + dRow + 16 * j, srcBh + ko + 16 * j);             \
    }

    // ---- fragment lane addressing (R11-proven) ----
    const uint32_t laneA = (uint32_t)((lane & 15) * ROWB + ((lane >> 4) << 4));
    const uint32_t laneB = (uint32_t)(((lane & 7) + ((lane >> 4) << 3)) * ROWB +
                                      (((lane >> 3) & 1) << 4));

    float acc[4][8][4];
#pragma unroll
    for (int mt = 0; mt < 4; ++mt)
#pragma unroll
        for (int nt = 0; nt < 8; ++nt)
#pragma unroll
            for (int e = 0; e < 4; ++e) acc[mt][nt][e] = 0.0f;

    // prologue: prefetch 3 chunks (nchunks >= 4 always)
#pragma unroll
    for (int i = 0; i < 3; ++i) { ISSUE_CP(i); CP_COMMIT(); }

    for (int c = 0; c < nchunks; ++c) {
        CP_WAIT2();
        __syncthreads();
        const uint32_t scur = sbase + (uint32_t)(c % NSTG) * STAGE;

#pragma unroll
        for (int ks = 0; ks < BK; ks += 16) {
            uint32_t bF[4][4], aH[4][4], aL[4][4];
            // B first: first MMA's operands are oldest in flight
#pragma unroll
            for (int ntp = 0; ntp < 4; ++ntp)
                ldm4(bF[ntp], scur + ST_BH +
                     (uint32_t)((n0w + 16 * ntp) * ROWB + ks * 2) + laneB);
#pragma unroll
            for (int mt = 0; mt < 4; ++mt) {
                const uint32_t ar = scur +
                    (uint32_t)((m0w + 16 * mt) * ROWB + ks * 2) + laneA;
                ldm4(aH[mt], ar);
            }
#pragma unroll
            for (int mt = 0; mt < 4; ++mt) {
                const uint32_t ar = scur + ST_AL +
                    (uint32_t)((m0w + 16 * mt) * ROWB + ks * 2) + laneA;
                ldm4(aL[mt], ar);
            }
            // term-major: dependent HMMAs 32 issues apart
#pragma unroll
            for (int mt = 0; mt < 4; ++mt)
#pragma unroll
                for (int nt = 0; nt < 8; ++nt)
                    mma_f16(acc[mt][nt], aH[mt],
                            bF[nt >> 1][(nt & 1) * 2], bF[nt >> 1][(nt & 1) * 2 + 1]);
#pragma unroll
            for (int mt = 0; mt < 4; ++mt)
#pragma unroll
                for (int nt = 0; nt < 8; ++nt)
                    mma_f16(acc[mt][nt], aL[mt],
                            bF[nt >> 1][(nt & 1) * 2], bF[nt >> 1][(nt & 1) * 2 + 1]);
        }

        __syncthreads();                     // all warps done reading stage c
        if (c + 3 < nchunks) ISSUE_CP(c + 3);
        CP_COMMIT();                         // keep group count invariant
    }

    // ---- epilogue: tril-masked stores ----
#pragma unroll
    for (int mt = 0; mt < 4; ++mt) {
        const int r0 = bm0 + m0w + 16 * mt + (lane >> 2);
#pragma unroll
        for (int nt = 0; nt < 8; ++nt) {
            const int c0 = bn0 + n0w + 8 * nt + 2 * (lane & 3);
            float* p0 = C + (size_t)r0 * NDIM + c0;
            float* p1 = p0 + 8 * (size_t)NDIM;
            if (c0     <= r0)     p0[0] = acc[mt][nt][0];
            if (c0 + 1 <= r0)     p0[1] = acc[mt][nt][1];
            if (c0     <= r0 + 8) p1[0] = acc[mt][nt][2];
            if (c0 + 1 <= r0 + 8) p1[1] = acc[mt][nt][3];
        }
    }
}

extern "C" void kernel_launch(void* const* d_in, const int* in_sizes, int n_in,
                              void* d_out, int out_size) {
    const float* A = (const float*)d_in[0];
    const float* B = (const float*)d_in[1];
    float* C = (float*)d_out;

    cudaFuncSetAttribute(trimm_f16, cudaFuncAttributeMaxDynamicSharedMemorySize,
                         SMEM_DYN);

    cudaMemsetAsync(C, 0, (size_t)NDIM * NDIM * sizeof(float), 0);

    prep_kernel<<<16384 + 4096, 256>>>(A, B);

    const int nblocks = NB * (NB + 1) / 2;   // 528 lower-triangular tiles
    trimm_f16<<<nblocks, THREADS, SMEM_DYN>>>(C);
}

// round 13
// speedup vs baseline: 1.0807x; 1.0807x over previous
#include <cuda_runtime.h>
#include <cuda_fp16.h>
#include <cstdint>
#include <math.h>

// tril(A @ B), A,B lower-triangular fp32, N=4096.
// R13: fp16 2-term split GEMM (rel_err 2.08e-4 validated), R11 geometry with
// register discipline so 2 CTAs x 256 thr (16 warps/SM) truly fit:
//   * 128x128 CTA tile, 8 warps in 2(m) x 4(n), warp tile 64x32
//   * A-fragments double-buffered across the mt loop (live frags 24, not 40)
//   * cp.async 3-stage ring from pre-split fp16 planes (no converts, no STS)
//   x = h + l (fp16 exact residual);  D = Ah*Bh + Al*Bh  (drop ~2^-11 term)

#define NDIM 4096
#define NB   32
#define BK   32
#define THREADS 256

#define ROWB  80               // 32 fp16 = 64B padded to 80B (conflict-free)
#define ST_AL 10240            // A hi at 0 (128*80), A lo, then B hi
#define ST_BH 20480
#define STAGE 30720
#define NSTG  3
#define SMEM_DYN (NSTG * STAGE)   // 92160/CTA; x2 CTAs = 184320 < 228KB

__device__ __align__(256) signed char g_Ah[(size_t)NDIM * NDIM * 2];
__device__ __align__(256) signed char g_Al[(size_t)NDIM * NDIM * 2];
__device__ __align__(256) signed char g_Bh[(size_t)NDIM * NDIM * 2];  // [n][k]

static __device__ __forceinline__ uint32_t smem_u32(const void* p) {
    uint32_t a;
    asm("{ .reg .u64 t; cvta.to.shared.u64 t, %1; cvt.u32.u64 %0, t; }"
        : "=r"(a) : "l"(p));
    return a;
}

static __device__ __forceinline__ uint32_t h2u(__half2 h) {
    return *reinterpret_cast<uint32_t*>(&h);
}

static __device__ __forceinline__ void split2(float x, float y,
                                              uint32_t& h, uint32_t& l) {
    __half2 hh = __floats2half2_rn(x, y);
    float rx = x - __half2float(__low2half(hh));
    float ry = y - __half2float(__high2half(hh));
    __half2 ll = __floats2half2_rn(rx, ry);
    h = h2u(hh);
    l = h2u(ll);
}

static __device__ __forceinline__ void ldm4(uint32_t d[4], uint32_t addr) {
    asm volatile("ldmatrix.sync.aligned.m8n8.x4.shared.b16 {%0,%1,%2,%3}, [%4];"
                 : "=r"(d[0]), "=r"(d[1]), "=r"(d[2]), "=r"(d[3]) : "r"(addr));
}

static __device__ __forceinline__ void mma_f16(float* c, const uint32_t* a,
                                               uint32_t b0, uint32_t b1) {
    asm volatile(
        "mma.sync.aligned.m16n8k16.row.col.f32.f16.f16.f32 "
        "{%0,%1,%2,%3}, {%4,%5,%6,%7}, {%8,%9}, {%0,%1,%2,%3};"
        : "+f"(c[0]), "+f"(c[1]), "+f"(c[2]), "+f"(c[3])
        : "r"(a[0]), "r"(a[1]), "r"(a[2]), "r"(a[3]), "r"(b0), "r"(b1));
}

static __device__ __forceinline__ void cp16(uint32_t dst, const void* src) {
    asm volatile("cp.async.cg.shared.global [%0], [%1], 16;"
                 :: "r"(dst), "l"(src) : "memory");
}
#define CP_COMMIT() asm volatile("cp.async.commit_group;" ::: "memory")
#define CP_WAIT2()  asm volatile("cp.async.wait_group 2;" ::: "memory")

// ---------------- merged prepass: A -> hi/lo planes; B -> Bh^T [n][k]
__global__ __launch_bounds__(256)
void prep_kernel(const float* __restrict__ A, const float* __restrict__ B) {
    __shared__ float tile[64][65];
    if (blockIdx.x < 16384) {
        const size_t i4 = ((size_t)blockIdx.x * 256 + threadIdx.x) * 4;
        float4 v = *(const float4*)(A + i4);
        uint32_t h01, l01, h23, l23;
        split2(v.x, v.y, h01, l01);
        split2(v.z, v.w, h23, l23);
        *(uint2*)(g_Ah + i4 * 2) = make_uint2(h01, h23);
        *(uint2*)(g_Al + i4 * 2) = make_uint2(l01, l23);
    } else {
        const int bb = blockIdx.x - 16384;
        const int tid = threadIdx.x;
        const int kt = (bb & 63) * 64;
        const int nt = (bb >> 6) * 64;
        {
            const int nc4 = (tid & 15) * 4;
            const int kr0 = tid >> 4;
#pragma unroll
            for (int j = 0; j < 4; ++j) {
                const int kr = kr0 + 16 * j;
                float4 v = *(const float4*)(B + (size_t)(kt + kr) * NDIM + nt + nc4);
                tile[kr][nc4] = v.x; tile[kr][nc4 + 1] = v.y;
                tile[kr][nc4 + 2] = v.z; tile[kr][nc4 + 3] = v.w;
            }
        }
        __syncthreads();
        const int kw4 = (tid & 15) * 4;
        const int n0 = tid >> 4;
#pragma unroll
        for (int it = 0; it < 4; ++it) {
            const int n = n0 + 16 * it;
            __half2 h01 = __floats2half2_rn(tile[kw4][n], tile[kw4 + 1][n]);
            __half2 h23 = __floats2half2_rn(tile[kw4 + 2][n], tile[kw4 + 3][n]);
            const size_t o = ((size_t)(nt + n) * NDIM + kt + kw4) * 2;
            *(uint2*)(g_Bh + o) = make_uint2(h2u(h01), h2u(h23));
        }
    }
}

// ---------------- main GEMM
__global__ __launch_bounds__(THREADS, 2)
void trimm_f16(float* __restrict__ C)
{
    extern __shared__ __align__(128) char dyn_smem[];
    const uint32_t sbase = smem_u32(dyn_smem);

    const int tid  = threadIdx.x;
    const int wid  = tid >> 5;
    const int lane = tid & 31;

    // ---- block id -> (bi,bj), largest-K first ----
    int t = blockIdx.x;
    int g = (int)((sqrtf(8.0f * (float)t + 1.0f) - 1.0f) * 0.5f);
    while ((g + 1) * (g + 2) / 2 <= t) ++g;
    while (g * (g + 1) / 2 > t) --g;
    const int bj = t - g * (g + 1) / 2;
    const int bi = bj + (NB - 1) - g;
    const int bm0 = bi * 128, bn0 = bj * 128;
    const int nchunks = ((bm0 + 128) - bn0) >> 5;   // 4..128

    // warp grid 2(m) x 4(n): warp tile 64x32
    const int m0w = (wid & 1) * 64;
    const int n0w = (wid >> 1) * 32;

    // ---- cp.async: 6 cp16/thread/chunk (A hi 2, A lo 2, B hi 2) ----
    const int aRow = tid & 127;
    const int aH2  = tid >> 7;                      // 32B half of a 64B row
    const uint32_t dA = (uint32_t)(aRow * ROWB + 32 * aH2);
    const signed char* srcAh = g_Ah + ((size_t)(bm0 + aRow) * NDIM + bn0) * 2 + 32 * aH2;
    const signed char* srcAl = g_Al + ((size_t)(bm0 + aRow) * NDIM + bn0) * 2 + 32 * aH2;
    const signed char* srcBh = g_Bh + ((size_t)(bn0 + aRow) * NDIM + bn0) * 2 + 32 * aH2;

#define ISSUE_CP(c)                                                            \
    {                                                                          \
        const uint32_t sb = sbase + (uint32_t)((c) % NSTG) * STAGE;            \
        const int ko = (c) * (BK * 2);                                         \
        cp16(sb + dA,              srcAh + ko);                                \
        cp16(sb + dA + 16,         srcAh + ko + 16);                           \
        cp16(sb + ST_AL + dA,      srcAl + ko);                                \
        cp16(sb + ST_AL + dA + 16, srcAl + ko + 16);                           \
        cp16(sb + ST_BH + dA,      srcBh + ko);                                \
        cp16(sb + ST_BH + dA + 16, srcBh + ko + 16);                           \
    }

    // ---- fragment lane addressing (R11/R12-proven) ----
    const uint32_t laneA = (uint32_t)((lane & 15) * ROWB + ((lane >> 4) << 4));
    const uint32_t laneB = (uint32_t)(((lane & 7) + ((lane >> 4) << 3)) * ROWB +
                                      (((lane >> 3) & 1) << 4));

    float acc[4][4][4];
#pragma unroll
    for (int mt = 0; mt < 4; ++mt)
#pragma unroll
        for (int nt = 0; nt < 4; ++nt)
#pragma unroll
            for (int e = 0; e < 4; ++e) acc[mt][nt][e] = 0.0f;

    // prologue: prefetch 3 chunks (nchunks >= 4 always)
#pragma unroll
    for (int i = 0; i < 3; ++i) { ISSUE_CP(i); CP_COMMIT(); }

    for (int c = 0; c < nchunks; ++c) {
        CP_WAIT2();
        __syncthreads();
        const uint32_t scur = sbase + (uint32_t)(c % NSTG) * STAGE;

#pragma unroll
        for (int ks = 0; ks < BK; ks += 16) {
            uint32_t bF[2][4];
#pragma unroll
            for (int ntp = 0; ntp < 2; ++ntp)
                ldm4(bF[ntp], scur + ST_BH +
                     (uint32_t)((n0w + 16 * ntp) * ROWB + ks * 2) + laneB);

            // A-frags double-buffered across mt: live frags = 24 regs
            uint32_t aH[2][4], aL[2][4];
            {
                const uint32_t ar = scur + (uint32_t)(m0w * ROWB + ks * 2) + laneA;
                ldm4(aH[0], ar);
                ldm4(aL[0], ar + ST_AL);
            }
#pragma unroll
            for (int mt = 0; mt < 4; ++mt) {
                const int cur = mt & 1;
                if (mt < 3) {
                    const uint32_t ar = scur +
                        (uint32_t)((m0w + 16 * (mt + 1)) * ROWB + ks * 2) + laneA;
                    ldm4(aH[cur ^ 1], ar);
                    ldm4(aL[cur ^ 1], ar + ST_AL);
                }
#pragma unroll
                for (int nt = 0; nt < 4; ++nt)
                    mma_f16(acc[mt][nt], aH[cur],
                            bF[nt >> 1][(nt & 1) * 2], bF[nt >> 1][(nt & 1) * 2 + 1]);
#pragma unroll
                for (int nt = 0; nt < 4; ++nt)
                    mma_f16(acc[mt][nt], aL[cur],
                            bF[nt >> 1][(nt & 1) * 2], bF[nt >> 1][(nt & 1) * 2 + 1]);
            }
        }

        __syncthreads();                     // all warps done reading stage c
        if (c + 3 < nchunks) ISSUE_CP(c + 3);
        CP_COMMIT();                         // keep group count invariant
    }

    // ---- epilogue: tril-masked stores ----
#pragma unroll
    for (int mt = 0; mt < 4; ++mt) {
        const int r0 = bm0 + m0w + 16 * mt + (lane >> 2);
#pragma unroll
        for (int nt = 0; nt < 4; ++nt) {
            const int c0 = bn0 + n0w + 8 * nt + 2 * (lane & 3);
            float* p0 = C + (size_t)r0 * NDIM + c0;
            float* p1 = p0 + 8 * (size_t)NDIM;
            if (c0     <= r0)     p0[0] = acc[mt][nt][0];
            if (c0 + 1 <= r0)     p0[1] = acc[mt][nt][1];
            if (c0     <= r0 + 8) p1[0] = acc[mt][nt][2];
            if (c0 + 1 <= r0 + 8) p1[1] = acc[mt][nt][3];
        }
    }
}

extern "C" void kernel_launch(void* const* d_in, const int* in_sizes, int n_in,
                              void* d_out, int out_size) {
    const float* A = (const float*)d_in[0];
    const float* B = (const float*)d_in[1];
    float* C = (float*)d_out;

    cudaFuncSetAttribute(trimm_f16, cudaFuncAttributeMaxDynamicSharedMemorySize,
                         SMEM_DYN);

    cudaMemsetAsync(C, 0, (size_t)NDIM * NDIM * sizeof(float), 0);

    prep_kernel<<<16384 + 4096, 256>>>(A, B);

    const int nblocks = NB * (NB + 1) / 2;   // 528 lower-triangular tiles
    trimm_f16<<<nblocks, THREADS, SMEM_DYN>>>(C);
}

// round 14
// speedup vs baseline: 1.7209x; 1.5923x over previous
#include <cuda_runtime.h>
#include <cuda_fp16.h>
#include <cstdint>
#include <math.h>

// tril(A @ B), A,B lower-triangular fp32, N=4096.
// R14 = R5's measured-best schedule (LDG+convert+STS, 128x64 half-tiles,
// 1056 CTAs, 2 CTAs/SM, double-buffered BK=32 smem) with fp16 2-term split:
//   x = h + l,  h = fp16(x), l = fp16(x - h)   (exact residual)
//   D = Ah*Bh + Al*Bh        (dropped term ~2^-11; rel_err 2.08e-4 validated)
// vs R5: MMA count x2/3 (floor 138->92us), B single plane (-25% STS/LDS).

#define NDIM 4096
#define NB   32
#define BK   32
#define THREADS 256

#define A_ROWB 80              // 32 fp16 = 64B padded to 80B
#define ST_AH 0                // 128*80 = 10240
#define ST_AL 10240
#define ST_BH 20480            // 32 k-rows * 128B = 4096
#define STAGE 24576
#define SMEM_DYN (2 * STAGE)   // 49152/CTA; x2 CTAs = 98304 < 228KB

static __device__ __forceinline__ uint32_t smem_u32(const void* p) {
    uint32_t a;
    asm("{ .reg .u64 t; cvta.to.shared.u64 t, %1; cvt.u32.u64 %0, t; }"
        : "=r"(a) : "l"(p));
    return a;
}

static __device__ __forceinline__ uint32_t h2u(__half2 h) {
    return *reinterpret_cast<uint32_t*>(&h);
}

// split two fp32 -> hi fp16x2 and lo fp16x2 (x low half, y high half)
static __device__ __forceinline__ void split2(float x, float y,
                                              uint32_t& h, uint32_t& l) {
    __half2 hh = __floats2half2_rn(x, y);
    float rx = x - __half2float(__low2half(hh));
    float ry = y - __half2float(__high2half(hh));
    l = h2u(__floats2half2_rn(rx, ry));
    h = h2u(hh);
}

static __device__ __forceinline__ void ldm4(uint32_t d[4], uint32_t addr) {
    asm volatile("ldmatrix.sync.aligned.m8n8.x4.shared.b16 {%0,%1,%2,%3}, [%4];"
                 : "=r"(d[0]), "=r"(d[1]), "=r"(d[2]), "=r"(d[3]) : "r"(addr));
}
static __device__ __forceinline__ void ldm4t(uint32_t d[4], uint32_t addr) {
    asm volatile("ldmatrix.sync.aligned.m8n8.x4.trans.shared.b16 {%0,%1,%2,%3}, [%4];"
                 : "=r"(d[0]), "=r"(d[1]), "=r"(d[2]), "=r"(d[3]) : "r"(addr));
}

static __device__ __forceinline__ void mma_f16(float* c, const uint32_t* a,
                                               const uint32_t* b) {
    asm volatile(
        "mma.sync.aligned.m16n8k16.row.col.f32.f16.f16.f32 "
        "{%0,%1,%2,%3}, {%4,%5,%6,%7}, {%8,%9}, {%0,%1,%2,%3};"
        : "+f"(c[0]), "+f"(c[1]), "+f"(c[2]), "+f"(c[3])
        : "r"(a[0]), "r"(a[1]), "r"(a[2]), "r"(a[3]), "r"(b[0]), "r"(b[1]));
}

static __device__ __forceinline__ void split4(float4 v, uint32_t& h01, uint32_t& h23,
                                              uint32_t& l01, uint32_t& l23) {
    split2(v.x, v.y, h01, l01);
    split2(v.z, v.w, h23, l23);
}

static __device__ __forceinline__ void sts2(uint32_t addr, uint32_t a, uint32_t b) {
    asm volatile("st.shared.v2.b32 [%0], {%1,%2};" :: "r"(addr), "r"(a), "r"(b)
                 : "memory");
}

__global__ __launch_bounds__(THREADS, 2)
void trimm_f16(const float* __restrict__ A, const float* __restrict__ B,
               float* __restrict__ C)
{
    extern __shared__ __align__(128) char dyn_smem[];
    const uint32_t sbase = smem_u32(dyn_smem);

    const int tid  = threadIdx.x;
    const int wid  = tid >> 5;
    const int lane = tid & 31;

    // ---- block id -> (bi,bj,half), largest-K first ----
    const int bid  = blockIdx.x;
    const int t    = bid >> 1;
    const int half = bid & 1;
    int g = (int)((sqrtf(8.0f * (float)t + 1.0f) - 1.0f) * 0.5f);
    while ((g + 1) * (g + 2) / 2 <= t) ++g;
    while (g * (g + 1) / 2 > t) --g;
    const int bj = t - g * (g + 1) / 2;
    const int bi = bj + (NB - 1) - g;
    const int bm0 = bi * 128;
    const int bn0 = bj * 128 + half * 64;
    const int kStart = bn0;
    const int kEnd   = bm0 + 128;
    const int nchunks = (kEnd - kStart) >> 5;   // 2..128

    // warp grid: 4(m) x 2(n); warp tile 32x32
    const int m0w = (wid & 3) * 32;
    const int n0w = (wid >> 2) * 32;

    // ldmatrix lane address components (R5-proven)
    const uint32_t laneA    = (uint32_t)((lane & 15) * A_ROWB + ((lane >> 4) << 4));
    const uint32_t laneBRow = (uint32_t)((lane & 15) * 128);
    const uint32_t laneBCol = (uint32_t)((((lane >> 4) ^ (lane & 7)) << 4));

    // global load indices (R5-proven, coalesced)
    const int amRow = tid >> 3;            // 0..31 (+32 per pass, 4 passes)
    const int akOff = (tid & 7) * 4;       // k float offset
    const int bkRow = tid >> 4;            // 0..15 (+16 per pass, 2 passes)
    const int bnOff = (tid & 15) * 4;      // n float offset (0..60)

    float acc[2][4][4];
#pragma unroll
    for (int mt = 0; mt < 2; ++mt)
#pragma unroll
        for (int nt = 0; nt < 4; ++nt)
#pragma unroll
            for (int e = 0; e < 4; ++e) acc[mt][nt][e] = 0.0f;

    float4 ra[4], rb[2];

#define LOAD_CHUNK(k0)                                                          \
    {                                                                           \
        _Pragma("unroll")                                                       \
        for (int p = 0; p < 4; ++p)                                             \
            ra[p] = *(const float4*)(A + (size_t)(bm0 + amRow + p * 32) * NDIM  \
                                       + (k0) + akOff);                         \
        _Pragma("unroll")                                                       \
        for (int p = 0; p < 2; ++p)                                             \
            rb[p] = *(const float4*)(B + (size_t)((k0) + bkRow + p * 16) * NDIM \
                                       + bn0 + bnOff);                          \
    }

#define STORE_CHUNK(sbuf)                                                       \
    {                                                                           \
        _Pragma("unroll")                                                       \
        for (int p = 0; p < 4; ++p) {                                           \
            uint32_t h01, h23, l01, l23;                                        \
            split4(ra[p], h01, h23, l01, l23);                                  \
            uint32_t aoff = (uint32_t)((amRow + p * 32) * A_ROWB + akOff * 2);  \
            sts2((sbuf) + ST_AH + aoff, h01, h23);                              \
            sts2((sbuf) + ST_AL + aoff, l01, l23);                              \
        }                                                                       \
        _Pragma("unroll")                                                       \
        for (int p = 0; p < 2; ++p) {                                           \
            __half2 h0 = __floats2half2_rn(rb[p].x, rb[p].y);                   \
            __half2 h1 = __floats2half2_rn(rb[p].z, rb[p].w);                   \
            int kk = bkRow + p * 16;                                            \
            uint32_t boff = (uint32_t)(kk * 128 +                               \
                            ((bnOff * 2) ^ ((kk & 7) << 4)));                   \
            sts2((sbuf) + ST_BH + boff, h2u(h0), h2u(h1));                      \
        }                                                                       \
    }

    // prologue
    LOAD_CHUNK(kStart);
    STORE_CHUNK(sbase);
    __syncthreads();

    for (int c = 0; c < nchunks; ++c) {
        const uint32_t scur = sbase + (uint32_t)(c & 1) * STAGE;
        const bool more = (c + 1 < nchunks);
        if (more) LOAD_CHUNK(kStart + (c + 1) * BK);

#pragma unroll
        for (int ks = 0; ks < BK; ks += 16) {
            uint32_t aH[2][4], aL[2][4], bF[2][4];
#pragma unroll
            for (int mt = 0; mt < 2; ++mt) {
                uint32_t ar = scur + ST_AH +
                              (uint32_t)((m0w + 16 * mt) * A_ROWB + ks * 2) + laneA;
                ldm4(aH[mt], ar);
                ldm4(aL[mt], ar + (ST_AL - ST_AH));
            }
#pragma unroll
            for (int ntp = 0; ntp < 2; ++ntp) {
                uint32_t twoN0 = (uint32_t)((n0w + 16 * ntp) * 2);
                uint32_t br = scur + ST_BH + (uint32_t)(ks * 128) + laneBRow +
                              (twoN0 ^ laneBCol);
                ldm4t(bF[ntp], br);
            }
            // term-major: dependent HMMAs 8 apart
#pragma unroll
            for (int mt = 0; mt < 2; ++mt)
#pragma unroll
                for (int nt = 0; nt < 4; ++nt)
                    mma_f16(acc[mt][nt], aH[mt], &bF[nt >> 1][(nt & 1) * 2]);
#pragma unroll
            for (int mt = 0; mt < 2; ++mt)
#pragma unroll
                for (int nt = 0; nt < 4; ++nt)
                    mma_f16(acc[mt][nt], aL[mt], &bF[nt >> 1][(nt & 1) * 2]);
        }

        if (more) STORE_CHUNK(sbase + (uint32_t)((c + 1) & 1) * STAGE);
        __syncthreads();
    }

    // ---- epilogue: tril-masked stores ----
#pragma unroll
    for (int mt = 0; mt < 2; ++mt) {
        const int r0 = bm0 + m0w + 16 * mt + (lane >> 2);
#pragma unroll
        for (int nt = 0; nt < 4; ++nt) {
            const int c0 = bn0 + n0w + 8 * nt + 2 * (lane & 3);
            float* p0 = C + (size_t)r0 * NDIM + c0;
            float* p1 = p0 + 8 * (size_t)NDIM;
            if (c0     <= r0)     p0[0] = acc[mt][nt][0];
            if (c0 + 1 <= r0)     p0[1] = acc[mt][nt][1];
            if (c0     <= r0 + 8) p1[0] = acc[mt][nt][2];
            if (c0 + 1 <= r0 + 8) p1[1] = acc[mt][nt][3];
        }
    }
}

extern "C" void kernel_launch(void* const* d_in, const int* in_sizes, int n_in,
                              void* d_out, int out_size) {
    const float* A = (const float*)d_in[0];
    const float* B = (const float*)d_in[1];
    float* C = (float*)d_out;

    cudaFuncSetAttribute(trimm_f16, cudaFuncAttributeMaxDynamicSharedMemorySize,
                         SMEM_DYN);

    // zero output (kernel never writes the strict upper triangle)
    cudaMemsetAsync(C, 0, (size_t)NDIM * NDIM * sizeof(float), 0);

    const int nblocks = NB * (NB + 1);   // 1056 half-tiles
    trimm_f16<<<nblocks, THREADS, SMEM_DYN>>>(A, B, C);
}

// round 15
// speedup vs baseline: 1.8274x; 1.0619x over previous
#include <cuda_runtime.h>
#include <cuda_fp16.h>
#include <cstdint>
#include <math.h>

// tril(A @ B), A,B lower-triangular fp32, N=4096.
// R15 = R14 (best: 176us) with the A-tile SMEM layout fixed:
//   80B-padded rows (store-side ~3-way bank conflicts) -> 64B rows with
//   16B-chunk XOR swizzle (chunk ^= (r>>1)&3): stores 2 wf (conflict-free),
//   ldmatrix reads conflict-free (8-row groups cover all 32 banks).
// Numerics unchanged (validated rel_err 2.08e-4):
//   x = h + l (fp16 exact residual);  D = Ah*Bh + Al*Bh.

#define NDIM 4096
#define NB   32
#define BK   32
#define THREADS 256

#define ST_AH 0                // A hi: 128 rows * 64B = 8192
#define ST_AL 8192             // A lo: 8192
#define ST_BH 16384            // B hi: 32 k-rows * 128B = 4096
#define STAGE 20480
#define SMEM_DYN (2 * STAGE)   // 40960/CTA; x2 CTAs = 81920

static __device__ __forceinline__ uint32_t smem_u32(const void* p) {
    uint32_t a;
    asm("{ .reg .u64 t; cvta.to.shared.u64 t, %1; cvt.u32.u64 %0, t; }"
        : "=r"(a) : "l"(p));
    return a;
}

static __device__ __forceinline__ uint32_t h2u(__half2 h) {
    return *reinterpret_cast<uint32_t*>(&h);
}

// split two fp32 -> hi fp16x2 and lo fp16x2 (x low half, y high half)
static __device__ __forceinline__ void split2(float x, float y,
                                              uint32_t& h, uint32_t& l) {
    __half2 hh = __floats2half2_rn(x, y);
    float rx = x - __half2float(__low2half(hh));
    float ry = y - __half2float(__high2half(hh));
    l = h2u(__floats2half2_rn(rx, ry));
    h = h2u(hh);
}

static __device__ __forceinline__ void ldm4(uint32_t d[4], uint32_t addr) {
    asm volatile("ldmatrix.sync.aligned.m8n8.x4.shared.b16 {%0,%1,%2,%3}, [%4];"
                 : "=r"(d[0]), "=r"(d[1]), "=r"(d[2]), "=r"(d[3]) : "r"(addr));
}
static __device__ __forceinline__ void ldm4t(uint32_t d[4], uint32_t addr) {
    asm volatile("ldmatrix.sync.aligned.m8n8.x4.trans.shared.b16 {%0,%1,%2,%3}, [%4];"
                 : "=r"(d[0]), "=r"(d[1]), "=r"(d[2]), "=r"(d[3]) : "r"(addr));
}

static __device__ __forceinline__ void mma_f16(float* c, const uint32_t* a,
                                               const uint32_t* b) {
    asm volatile(
        "mma.sync.aligned.m16n8k16.row.col.f32.f16.f16.f32 "
        "{%0,%1,%2,%3}, {%4,%5,%6,%7}, {%8,%9}, {%0,%1,%2,%3};"
        : "+f"(c[0]), "+f"(c[1]), "+f"(c[2]), "+f"(c[3])
        : "r"(a[0]), "r"(a[1]), "r"(a[2]), "r"(a[3]), "r"(b[0]), "r"(b[1]));
}

static __device__ __forceinline__ void split4(float4 v, uint32_t& h01, uint32_t& h23,
                                              uint32_t& l01, uint32_t& l23) {
    split2(v.x, v.y, h01, l01);
    split2(v.z, v.w, h23, l23);
}

static __device__ __forceinline__ void sts2(uint32_t addr, uint32_t a, uint32_t b) {
    asm volatile("st.shared.v2.b32 [%0], {%1,%2};" :: "r"(addr), "r"(a), "r"(b)
                 : "memory");
}

__global__ __launch_bounds__(THREADS, 2)
void trimm_f16(const float* __restrict__ A, const float* __restrict__ B,
               float* __restrict__ C)
{
    extern __shared__ __align__(128) char dyn_smem[];
    const uint32_t sbase = smem_u32(dyn_smem);

    const int tid  = threadIdx.x;
    const int wid  = tid >> 5;
    const int lane = tid & 31;

    // ---- block id -> (bi,bj,half), largest-K first ----
    const int bid  = blockIdx.x;
    const int t    = bid >> 1;
    const int half = bid & 1;
    int g = (int)((sqrtf(8.0f * (float)t + 1.0f) - 1.0f) * 0.5f);
    while ((g + 1) * (g + 2) / 2 <= t) ++g;
    while (g * (g + 1) / 2 > t) --g;
    const int bj = t - g * (g + 1) / 2;
    const int bi = bj + (NB - 1) - g;
    const int bm0 = bi * 128;
    const int bn0 = bj * 128 + half * 64;
    const int kStart = bn0;
    const int kEnd   = bm0 + 128;
    const int nchunks = (kEnd - kStart) >> 5;   // 2..128

    // warp grid: 4(m) x 2(n); warp tile 32x32
    const int m0w = (wid & 3) * 32;
    const int n0w = (wid >> 2) * 32;

    // ---- A-tile ldmatrix lane address (64B rows, chunk ^= (r>>1)&3) ----
    // row-within-frag = lane&15 (16mt offsets are multiples of 16 -> swizzle
    // key depends only on lane); chunk bits live at [4:6).
    const uint32_t swL   = (uint32_t)(((lane & 15) >> 1) & 3);
    const uint32_t laneA = (uint32_t)((lane & 15) * 64) +
                           ((((uint32_t)(lane >> 4)) ^ swL) << 4);
    // B tile (unchanged from R14; verified conflict-free)
    const uint32_t laneBRow = (uint32_t)((lane & 15) * 128);
    const uint32_t laneBCol = (uint32_t)((((lane >> 4) ^ (lane & 7)) << 4));

    // ---- global load + A-store indices ----
    const int amRow = tid >> 3;            // 0..31 (+32 per pass, 4 passes)
    const int akOff = (tid & 7) * 4;       // k float offset
    const int bkRow = tid >> 4;            // 0..15 (+16 per pass, 2 passes)
    const int bnOff = (tid & 15) * 4;      // n float offset (0..60)
    // A store: row amRow(+32p), fp16 bytes (tid&7)*8 -> chunk=(tid&7)>>1,
    // 8B half=(tid&1); swizzle key (r>>1)&3 == (tid>>4)&3 (32p = 0 mod 4 rows)
    const uint32_t aoffBase = (uint32_t)(amRow * 64) +
        ((((uint32_t)((tid & 7) >> 1)) ^ ((uint32_t)(tid >> 4) & 3u)) << 4) +
        (uint32_t)((tid & 1) * 8);

    float acc[2][4][4];
#pragma unroll
    for (int mt = 0; mt < 2; ++mt)
#pragma unroll
        for (int nt = 0; nt < 4; ++nt)
#pragma unroll
            for (int e = 0; e < 4; ++e) acc[mt][nt][e] = 0.0f;

    float4 ra[4], rb[2];

#define LOAD_CHUNK(k0)                                                          \
    {                                                                           \
        _Pragma("unroll")                                                       \
        for (int p = 0; p < 4; ++p)                                             \
            ra[p] = *(const float4*)(A + (size_t)(bm0 + amRow + p * 32) * NDIM  \
                                       + (k0) + akOff);                         \
        _Pragma("unroll")                                                       \
        for (int p = 0; p < 2; ++p)                                             \
            rb[p] = *(const float4*)(B + (size_t)((k0) + bkRow + p * 16) * NDIM \
                                       + bn0 + bnOff);                          \
    }

#define STORE_CHUNK(sbuf)                                                       \
    {                                                                           \
        _Pragma("unroll")                                                       \
        for (int p = 0; p < 4; ++p) {                                           \
            uint32_t h01, h23, l01, l23;                                        \
            split4(ra[p], h01, h23, l01, l23);                                  \
            uint32_t aoff = aoffBase + (uint32_t)(p * 2048);                    \
            sts2((sbuf) + ST_AH + aoff, h01, h23);                              \
            sts2((sbuf) + ST_AL + aoff, l01, l23);                              \
        }                                                                       \
        _Pragma("unroll")                                                       \
        for (int p = 0; p < 2; ++p) {                                           \
            __half2 h0 = __floats2half2_rn(rb[p].x, rb[p].y);                   \
            __half2 h1 = __floats2half2_rn(rb[p].z, rb[p].w);                   \
            int kk = bkRow + p * 16;                                            \
            uint32_t boff = (uint32_t)(kk * 128 +                               \
                            ((bnOff * 2) ^ ((kk & 7) << 4)));                   \
            sts2((sbuf) + ST_BH + boff, h2u(h0), h2u(h1));                      \
        }                                                                       \
    }

    // prologue
    LOAD_CHUNK(kStart);
    STORE_CHUNK(sbase);
    __syncthreads();

    for (int c = 0; c < nchunks; ++c) {
        const uint32_t scur = sbase + (uint32_t)(c & 1) * STAGE;
        const bool more = (c + 1 < nchunks);
        if (more) LOAD_CHUNK(kStart + (c + 1) * BK);

#pragma unroll
        for (int ks = 0; ks < BK; ks += 16) {
            uint32_t aH[2][4], aL[2][4], bF[2][4];
#pragma unroll
            for (int mt = 0; mt < 2; ++mt) {
                // k-chunk select XORs into swizzled chunk bits [4:6)
                uint32_t ar = scur + ST_AH +
                              (uint32_t)((m0w + 16 * mt) * 64) +
                              (laneA ^ (uint32_t)((ks >> 3) << 4));
                ldm4(aH[mt], ar);
                ldm4(aL[mt], ar + (ST_AL - ST_AH));
            }
#pragma unroll
            for (int ntp = 0; ntp < 2; ++ntp) {
                uint32_t twoN0 = (uint32_t)((n0w + 16 * ntp) * 2);
                uint32_t br = scur + ST_BH + (uint32_t)(ks * 128) + laneBRow +
                              (twoN0 ^ laneBCol);
                ldm4t(bF[ntp], br);
            }
            // term-major: dependent HMMAs 8 apart
#pragma unroll
            for (int mt = 0; mt < 2; ++mt)
#pragma unroll
                for (int nt = 0; nt < 4; ++nt)
                    mma_f16(acc[mt][nt], aH[mt], &bF[nt >> 1][(nt & 1) * 2]);
#pragma unroll
            for (int mt = 0; mt < 2; ++mt)
#pragma unroll
                for (int nt = 0; nt < 4; ++nt)
                    mma_f16(acc[mt][nt], aL[mt], &bF[nt >> 1][(nt & 1) * 2]);
        }

        if (more) STORE_CHUNK(sbase + (uint32_t)((c + 1) & 1) * STAGE);
        __syncthreads();
    }

    // ---- epilogue: tril-masked stores ----
#pragma unroll
    for (int mt = 0; mt < 2; ++mt) {
        const int r0 = bm0 + m0w + 16 * mt + (lane >> 2);
#pragma unroll
        for (int nt = 0; nt < 4; ++nt) {
            const int c0 = bn0 + n0w + 8 * nt + 2 * (lane & 3);
            float* p0 = C + (size_t)r0 * NDIM + c0;
            float* p1 = p0 + 8 * (size_t)NDIM;
            if (c0     <= r0)     p0[0] = acc[mt][nt][0];
            if (c0 + 1 <= r0)     p0[1] = acc[mt][nt][1];
            if (c0     <= r0 + 8) p1[0] = acc[mt][nt][2];
            if (c0 + 1 <= r0 + 8) p1[1] = acc[mt][nt][3];
        }
    }
}

extern "C" void kernel_launch(void* const* d_in, const int* in_sizes, int n_in,
                              void* d_out, int out_size) {
    const float* A = (const float*)d_in[0];
    const float* B = (const float*)d_in[1];
    float* C = (float*)d_out;

    cudaFuncSetAttribute(trimm_f16, cudaFuncAttributeMaxDynamicSharedMemorySize,
                         SMEM_DYN);

    // zero output (kernel never writes the strict upper triangle)
    cudaMemsetAsync(C, 0, (size_t)NDIM * NDIM * sizeof(float), 0);

    const int nblocks = NB * (NB + 1);   // 1056 half-tiles
    trimm_f16<<<nblocks, THREADS, SMEM_DYN>>>(A, B, C);
}